// round 3
// baseline (speedup 1.0000x reference)
#include <cuda_runtime.h>

// Problem constants
#define Bn 64
#define Tn 4096
#define Fn 128
#define Hn 512
#define On 10
#define DTc 0.1f

// Decomposition: 16 clusters x 8 CTAs; each cluster owns 4 batch rows;
// each CTA owns a 64-column slice of H and keeps its [W_rec;W_in] slice
// (640 x 64 fp32, transposed + padded) resident in SMEM for all 4096 steps.
#define CLUSTER 8
#define ROWSn 4            // batch rows per cluster
#define COLSn 64           // Hn / CLUSTER
#define KTOT 640           // Hn + Fn  (augmented input [s ; x_t])
#define KGn 4              // k-groups (== ROWSn, reused in finalize)
#define KPG 160            // KTOT / KGn
#define NT 256             // threads per CTA
#define WPAD 644           // padded column stride (16B aligned, conflict-free LDS.128)

// SMEM layout (in floats)
#define OFF_WT 0
#define SZ_WT (COLSn * WPAD)              // 41216
#define OFF_V (OFF_WT + SZ_WT)            // double-buffered [s(512) ; x(128)] per row
#define SZ_V (2 * ROWSn * KTOT)           // 5120
#define OFF_P (OFF_V + SZ_V)              // partial sums [r][hh][kg]
#define SZ_P (ROWSn * COLSn * KGn)        // 1024
#define OFF_B (OFF_P + SZ_P)              // bias slice
#define OFF_D (OFF_B + COLSn)             // DT / tau slice
#define SMEM_FLOATS (OFF_D + COLSn)
#define SMEM_BYTES (SMEM_FLOATS * 4)      // 189,952 B

__device__ __forceinline__ unsigned smem_u32(const void* p) {
    return (unsigned)__cvta_generic_to_shared(p);
}

__device__ __forceinline__ void cluster_sync_all() {
    asm volatile("barrier.cluster.arrive.aligned;\n\t"
                 "barrier.cluster.wait.aligned;" ::: "memory");
}

extern __shared__ float smem[];

__global__ void __launch_bounds__(NT, 1) __cluster_dims__(CLUSTER, 1, 1)
ctrnn_kernel(const float* __restrict__ x, const float* __restrict__ ic,
             const float* __restrict__ Win, const float* __restrict__ Wrec,
             const float* __restrict__ bias, const float* __restrict__ tau,
             const float* __restrict__ rw, const float* __restrict__ rb,
             float* __restrict__ out)
{
    const int tid = threadIdx.x;
    const int rank = (int)(blockIdx.x & (CLUSTER - 1));   // CTA rank within cluster
    const int clid = (int)(blockIdx.x >> 3);              // cluster id (0..15)
    const int hbase = rank * COLSn;                       // my H-column slice
    const int rbase = clid * ROWSn;                       // my batch rows

    float* Wt = smem + OFF_WT;   // [hh][k] transposed, stride WPAD
    float* V  = smem + OFF_V;    // 2 x [ROWSn][KTOT]
    float* P  = smem + OFF_P;    // [r][hh][kg]
    float* Bs = smem + OFF_B;
    float* Di = smem + OFF_D;

    // ---------------- prologue: load resident weight slice (transposed) ----------------
    {
        const int hh = tid & 63;
        for (int k = (tid >> 6); k < KTOT; k += 4) {
            float w = (k < Hn) ? Wrec[(size_t)k * Hn + hbase + hh]
                               : Win[(size_t)(k - Hn) * Hn + hbase + hh];
            Wt[hh * WPAD + k] = w;
        }
    }
    if (tid < COLSn) {
        Bs[tid] = bias[hbase + tid];
        Di[tid] = DTc / tau[hbase + tid];
    }
    // init state buffer 0 with trainable IC (same ic for every batch row)
    for (int i = tid; i < ROWSn * Hn; i += NT) {
        int r = i >> 9, k = i & (Hn - 1);
        V[r * KTOT + k] = ic[k];
    }
    // x[t=0] into buffer 0
    if (tid < 128) {
        int r = tid >> 5, j = tid & 31;
        const float4 xv = *reinterpret_cast<const float4*>(
            x + ((size_t)(rbase + r) * Tn) * Fn + 4 * j);
        *reinterpret_cast<float4*>(&V[r * KTOT + Hn + 4 * j]) = xv;
    }
    __syncthreads();
    cluster_sync_all();

    const int kg = tid >> 6;     // k-group 0..3
    const int hh = tid & 63;     // column within slice
    const float* wcol = &Wt[hh * WPAD + kg * KPG];
    const float dti = Di[hh];
    const float bi  = Bs[hh];

    int cur = 0;
    for (int t = 0; t < Tn; ++t) {
        float* vc = V + cur * (ROWSn * KTOT);
        float* vn = V + (cur ^ 1) * (ROWSn * KTOT);

        // ---- prefetch x[t+1] into next buffer (cp.async, hidden under compute) ----
        if (tid < 128) {
            if (t + 1 < Tn) {
                int r = tid >> 5, j = tid & 31;
                const float* src = x + ((size_t)(rbase + r) * Tn + (t + 1)) * Fn + 4 * j;
                unsigned dst = smem_u32(&vn[r * KTOT + Hn + 4 * j]);
                asm volatile("cp.async.cg.shared.global [%0], [%1], 16;"
                             :: "r"(dst), "l"(src));
            }
            asm volatile("cp.async.commit_group;");
            asm volatile("cp.async.wait_group 1;");   // completes last step's prefetch
        }
        __syncthreads();  // publish x[t] to all warps

        // ---- pre[r][hh] partial over this thread's k-range ----
        const float* vkg = vc + kg * KPG;
        float a0 = 0.f, a1 = 0.f, a2 = 0.f, a3 = 0.f;
        #pragma unroll 4
        for (int i = 0; i < KPG; i += 4) {
            float4 w  = *reinterpret_cast<const float4*>(wcol + i);
            float4 q0 = *reinterpret_cast<const float4*>(vkg + i);
            float4 q1 = *reinterpret_cast<const float4*>(vkg + KTOT + i);
            float4 q2 = *reinterpret_cast<const float4*>(vkg + 2 * KTOT + i);
            float4 q3 = *reinterpret_cast<const float4*>(vkg + 3 * KTOT + i);
            a0 = fmaf(w.x, q0.x, a0); a0 = fmaf(w.y, q0.y, a0);
            a0 = fmaf(w.z, q0.z, a0); a0 = fmaf(w.w, q0.w, a0);
            a1 = fmaf(w.x, q1.x, a1); a1 = fmaf(w.y, q1.y, a1);
            a1 = fmaf(w.z, q1.z, a1); a1 = fmaf(w.w, q1.w, a1);
            a2 = fmaf(w.x, q2.x, a2); a2 = fmaf(w.y, q2.y, a2);
            a2 = fmaf(w.z, q2.z, a2); a2 = fmaf(w.w, q2.w, a2);
            a3 = fmaf(w.x, q3.x, a3); a3 = fmaf(w.y, q3.y, a3);
            a3 = fmaf(w.z, q3.z, a3); a3 = fmaf(w.w, q3.w, a3);
        }
        P[(0 * COLSn + hh) * KGn + kg] = a0;
        P[(1 * COLSn + hh) * KGn + kg] = a1;
        P[(2 * COLSn + hh) * KGn + kg] = a2;
        P[(3 * COLSn + hh) * KGn + kg] = a3;
        __syncthreads();

        // ---- finalize (thread handles row r = kg, column hh) + broadcast s' ----
        {
            const int r = kg;
            const float4 pp = *reinterpret_cast<const float4*>(&P[(r * COLSn + hh) * KGn]);
            float pre  = ((pp.x + pp.y) + (pp.z + pp.w)) + bi;
            float sold = vc[r * KTOT + hbase + hh];
            float th   = tanhf(pre);
            float sn   = sold + dti * (th - sold);   // s + DT*(-s+tanh)/tau
            unsigned my = smem_u32(&vn[r * KTOT + hbase + hh]);
            #pragma unroll
            for (int c = 0; c < CLUSTER; ++c) {
                unsigned ra;
                asm("mapa.shared::cluster.u32 %0, %1, %2;" : "=r"(ra) : "r"(my), "r"(c));
                asm volatile("st.shared::cluster.f32 [%0], %1;" :: "r"(ra), "f"(sn));
            }
        }
        cluster_sync_all();   // release my pushes / acquire peers' pushes
        cur ^= 1;
    }

    // ---------------- readout of final state (rank 0 of each cluster) ----------------
    if (rank == 0 && tid < ROWSn * On) {
        const int r = tid / On, o = tid - On * r;
        const float* s = V + cur * (ROWSn * KTOT) + r * KTOT;
        float c0 = 0.f, c1 = 0.f, c2 = 0.f, c3 = 0.f;
        #pragma unroll 8
        for (int k = 0; k < Hn; k += 4) {
            c0 = fmaf(s[k    ], rw[(k    ) * On + o], c0);
            c1 = fmaf(s[k + 1], rw[(k + 1) * On + o], c1);
            c2 = fmaf(s[k + 2], rw[(k + 2) * On + o], c2);
            c3 = fmaf(s[k + 3], rw[(k + 3) * On + o], c3);
        }
        out[(rbase + r) * On + o] = (c0 + c1) + (c2 + c3) + rb[o];
    }
}

extern "C" void kernel_launch(void* const* d_in, const int* in_sizes, int n_in,
                              void* d_out, int out_size) {
    const float* x    = (const float*)d_in[0];
    const float* ic   = (const float*)d_in[1];
    const float* Win  = (const float*)d_in[2];
    const float* Wrec = (const float*)d_in[3];
    const float* b    = (const float*)d_in[4];
    const float* tau  = (const float*)d_in[5];
    const float* rw   = (const float*)d_in[6];
    const float* rb   = (const float*)d_in[7];
    float* out = (float*)d_out;

    cudaFuncSetAttribute(ctrnn_kernel,
                         cudaFuncAttributeMaxDynamicSharedMemorySize, SMEM_BYTES);
    // 16 clusters x 8 CTAs (cluster dims baked via __cluster_dims__)
    ctrnn_kernel<<<(Bn / ROWSn) * CLUSTER, NT, SMEM_BYTES>>>(
        x, ic, Win, Wrec, b, tau, rw, rb, out);
}

// round 4
// speedup vs baseline: 1.6312x; 1.6312x over previous
#include <cuda_runtime.h>

// Problem constants
#define Bn 64
#define Tn 4096
#define Fn 128
#define Hn 512
#define On 10
#define DTc 0.1f

// Decomposition: 16 clusters x 8 CTAs; cluster owns 4 batch rows; CTA owns a
// 64-column slice of H. Weights now live in REGISTERS: each thread holds a
// 40(k) x 4(col) fp32 tile of [W_rec;W_in] (160 regs), so the per-step smem
// traffic is only the broadcast q loads + tiny partial exchange.
#define CLUSTER 8
#define ROWSn 4            // batch rows per cluster
#define COLSn 64           // Hn / CLUSTER
#define KTOT 640           // Hn + Fn  (augmented [s ; x_t])
#define NT 256
#define KEXT 40            // k-extent per thread (KTOT / NKG)
#define NKG 16             // k-groups
#define NCG 16             // col-groups (x4 cols each = 64)

// SMEM layout (floats)
#define OFF_V 0                            // double-buffered [s(512);x(128)] per row
#define SZ_V (2 * ROWSn * KTOT)            // 5120
#define OFF_P (OFF_V + SZ_V)               // partials [r][kg][hh]
#define SZ_P (ROWSn * NKG * COLSn)         // 4096
#define OFF_B (OFF_P + SZ_P)
#define OFF_D (OFF_B + COLSn)
#define SMEM_FLOATS (OFF_D + COLSn)
#define SMEM_BYTES (SMEM_FLOATS * 4)       // ~37.6 KB

__device__ __forceinline__ unsigned smem_u32(const void* p) {
    return (unsigned)__cvta_generic_to_shared(p);
}

__device__ __forceinline__ void cluster_sync_all() {
    asm volatile("barrier.cluster.arrive.aligned;\n\t"
                 "barrier.cluster.wait.aligned;" ::: "memory");
}

extern __shared__ float smem[];

__global__ void __launch_bounds__(NT, 1) __cluster_dims__(CLUSTER, 1, 1)
ctrnn_kernel(const float* __restrict__ x, const float* __restrict__ ic,
             const float* __restrict__ Win, const float* __restrict__ Wrec,
             const float* __restrict__ bias, const float* __restrict__ tau,
             const float* __restrict__ rw, const float* __restrict__ rb,
             float* __restrict__ out)
{
    const int tid = threadIdx.x;
    const int rank = (int)(blockIdx.x & (CLUSTER - 1));
    const int clid = (int)(blockIdx.x >> 3);
    const int hbase = rank * COLSn;
    const int rbase = clid * ROWSn;

    float* V  = smem + OFF_V;    // 2 x [ROWSn][KTOT]
    float* P  = smem + OFF_P;    // [r][kg][hh]
    float* Bs = smem + OFF_B;
    float* Di = smem + OFF_D;

    const int kg = tid >> 4;             // 0..15  k-group
    const int cg = tid & 15;             // 0..15  col-group (4 cols)
    const int kbase = kg * KEXT;
    const int cbase = hbase + cg * 4;

    // ---- register-resident weight tile: w4[kk] = W[kbase+kk][cbase..cbase+3] ----
    float4 w4[KEXT];
    #pragma unroll
    for (int kk = 0; kk < KEXT; ++kk) {
        const int k = kbase + kk;
        const float* src = (k < Hn) ? (Wrec + (size_t)k * Hn + cbase)
                                    : (Win + (size_t)(k - Hn) * Hn + cbase);
        w4[kk] = *reinterpret_cast<const float4*>(src);
    }

    if (tid < COLSn) {
        Bs[tid] = bias[hbase + tid];
        Di[tid] = DTc / tau[hbase + tid];
    }
    // init state buffer 0 with trainable IC
    for (int i = tid; i < ROWSn * Hn; i += NT) {
        int r = i >> 9, k = i & (Hn - 1);
        V[r * KTOT + k] = ic[k];
    }
    // x[t=0] into buffer 0
    if (tid < 128) {
        int r = tid >> 5, j = tid & 31;
        const float4 xv = *reinterpret_cast<const float4*>(
            x + ((size_t)(rbase + r) * Tn) * Fn + 4 * j);
        *reinterpret_cast<float4*>(&V[r * KTOT + Hn + 4 * j]) = xv;
    }
    __syncthreads();

    // finalize-thread constants (mapping: r = tid>>6, hh = tid&63)
    const int fr = tid >> 6;
    const int fh = tid & 63;
    float bi, dti;
    {
        bi  = Bs[fh];
        dti = Di[fh];
    }
    cluster_sync_all();

    int cur = 0;
    for (int t = 0; t < Tn; ++t) {
        float* vc = V + cur * (ROWSn * KTOT);
        float* vn = V + (cur ^ 1) * (ROWSn * KTOT);

        // ---- prefetch x[t+1] into next buffer ----
        if (tid < 128) {
            if (t + 1 < Tn) {
                int r = tid >> 5, j = tid & 31;
                const float* src = x + ((size_t)(rbase + r) * Tn + (t + 1)) * Fn + 4 * j;
                unsigned dst = smem_u32(&vn[r * KTOT + Hn + 4 * j]);
                asm volatile("cp.async.cg.shared.global [%0], [%1], 16;"
                             :: "r"(dst), "l"(src));
            }
            asm volatile("cp.async.commit_group;");
            asm volatile("cp.async.wait_group 1;");   // completes last step's prefetch
        }
        __syncthreads();  // publish x[t]

        // ---- GEMV partial: acc[r][c] over this thread's 40-k range ----
        const float* vkg = vc + kbase;
        float acc[ROWSn][4];
        #pragma unroll
        for (int r = 0; r < ROWSn; ++r)
            { acc[r][0] = 0.f; acc[r][1] = 0.f; acc[r][2] = 0.f; acc[r][3] = 0.f; }

        #pragma unroll
        for (int kb = 0; kb < KEXT / 4; ++kb) {
            const float4 w0 = w4[kb * 4 + 0];
            const float4 w1 = w4[kb * 4 + 1];
            const float4 w2 = w4[kb * 4 + 2];
            const float4 w3 = w4[kb * 4 + 3];
            #pragma unroll
            for (int r = 0; r < ROWSn; ++r) {
                const float4 q = *reinterpret_cast<const float4*>(vkg + r * KTOT + kb * 4);
                acc[r][0] = fmaf(q.x, w0.x, acc[r][0]);
                acc[r][0] = fmaf(q.y, w1.x, acc[r][0]);
                acc[r][0] = fmaf(q.z, w2.x, acc[r][0]);
                acc[r][0] = fmaf(q.w, w3.x, acc[r][0]);
                acc[r][1] = fmaf(q.x, w0.y, acc[r][1]);
                acc[r][1] = fmaf(q.y, w1.y, acc[r][1]);
                acc[r][1] = fmaf(q.z, w2.y, acc[r][1]);
                acc[r][1] = fmaf(q.w, w3.y, acc[r][1]);
                acc[r][2] = fmaf(q.x, w0.z, acc[r][2]);
                acc[r][2] = fmaf(q.y, w1.z, acc[r][2]);
                acc[r][2] = fmaf(q.z, w2.z, acc[r][2]);
                acc[r][2] = fmaf(q.w, w3.z, acc[r][2]);
                acc[r][3] = fmaf(q.x, w0.w, acc[r][3]);
                acc[r][3] = fmaf(q.y, w1.w, acc[r][3]);
                acc[r][3] = fmaf(q.z, w2.w, acc[r][3]);
                acc[r][3] = fmaf(q.w, w3.w, acc[r][3]);
            }
        }
        // store partials: P[r][kg][cg*4 .. +3]  (float4, conflict-free)
        #pragma unroll
        for (int r = 0; r < ROWSn; ++r) {
            *reinterpret_cast<float4*>(&P[(r * NKG + kg) * COLSn + cg * 4]) =
                make_float4(acc[r][0], acc[r][1], acc[r][2], acc[r][3]);
        }
        __syncthreads();

        // ---- reduce 16 partials, finalize, push s' to all 8 CTAs ----
        {
            const float* pr = &P[fr * NKG * COLSn + fh];
            float s0 = 0.f, s1 = 0.f;
            #pragma unroll
            for (int g = 0; g < NKG; g += 2) {
                s0 += pr[g * COLSn];
                s1 += pr[(g + 1) * COLSn];
            }
            float pre  = (s0 + s1) + bi;
            float sold = vc[fr * KTOT + hbase + fh];
            float th   = tanhf(pre);
            float sn   = sold + dti * (th - sold);
            unsigned my = smem_u32(&vn[fr * KTOT + hbase + fh]);
            #pragma unroll
            for (int c = 0; c < CLUSTER; ++c) {
                unsigned ra;
                asm("mapa.shared::cluster.u32 %0, %1, %2;" : "=r"(ra) : "r"(my), "r"(c));
                asm volatile("st.shared::cluster.f32 [%0], %1;" :: "r"(ra), "f"(sn));
            }
        }
        cluster_sync_all();
        cur ^= 1;
    }

    // ---------------- readout (rank 0 of each cluster) ----------------
    if (rank == 0 && tid < ROWSn * On) {
        const int r = tid / On, o = tid - On * r;
        const float* s = V + cur * (ROWSn * KTOT) + r * KTOT;
        float c0 = 0.f, c1 = 0.f, c2 = 0.f, c3 = 0.f;
        #pragma unroll 8
        for (int k = 0; k < Hn; k += 4) {
            c0 = fmaf(s[k    ], rw[(k    ) * On + o], c0);
            c1 = fmaf(s[k + 1], rw[(k + 1) * On + o], c1);
            c2 = fmaf(s[k + 2], rw[(k + 2) * On + o], c2);
            c3 = fmaf(s[k + 3], rw[(k + 3) * On + o], c3);
        }
        out[(rbase + r) * On + o] = (c0 + c1) + (c2 + c3) + rb[o];
    }
}

extern "C" void kernel_launch(void* const* d_in, const int* in_sizes, int n_in,
                              void* d_out, int out_size) {
    const float* x    = (const float*)d_in[0];
    const float* ic   = (const float*)d_in[1];
    const float* Win  = (const float*)d_in[2];
    const float* Wrec = (const float*)d_in[3];
    const float* b    = (const float*)d_in[4];
    const float* tau  = (const float*)d_in[5];
    const float* rw   = (const float*)d_in[6];
    const float* rb   = (const float*)d_in[7];
    float* out = (float*)d_out;

    cudaFuncSetAttribute(ctrnn_kernel,
                         cudaFuncAttributeMaxDynamicSharedMemorySize, SMEM_BYTES);
    ctrnn_kernel<<<(Bn / ROWSn) * CLUSTER, NT, SMEM_BYTES>>>(
        x, ic, Win, Wrec, b, tau, rw, rb, out);
}

// round 5
// speedup vs baseline: 1.7719x; 1.0863x over previous
#include <cuda_runtime.h>

// Problem constants
#define Bn 64
#define Tn 4096
#define Fn 128
#define Hn 512
#define On 10
#define DTc 0.1f

// 16 clusters x 8 CTAs; cluster owns 4 batch rows; CTA owns a 64-column slice
// of H. Weights register-resident as k-pair-packed f32x2 operands; the GEMV
// inner loop runs entirely on fma.rn.f32x2 (2 FMA/lane/issue).
#define CLUSTER 8
#define ROWSn 4
#define COLSn 64
#define KTOT 640           // Hn + Fn
#define NT 256
#define KEXT 40            // k-extent per thread
#define NKG 16             // k-groups
#define KP2 (KEXT / 2)     // packed k-pairs per thread (20)

// SMEM layout (floats)
#define OFF_V 0                            // double-buffered [s(512);x(128)] per row
#define SZ_V (2 * ROWSn * KTOT)            // 5120
#define OFF_P (OFF_V + SZ_V)               // partials [r][kg][hh]
#define SZ_P (ROWSn * NKG * COLSn)         // 4096
#define OFF_B (OFF_P + SZ_P)
#define OFF_D (OFF_B + COLSn)
#define SMEM_FLOATS (OFF_D + COLSn)
#define SMEM_BYTES (SMEM_FLOATS * 4)       // ~37.6 KB

__device__ __forceinline__ unsigned smem_u32(const void* p) {
    return (unsigned)__cvta_generic_to_shared(p);
}

__device__ __forceinline__ void cluster_sync_all() {
    asm volatile("barrier.cluster.arrive.aligned;\n\t"
                 "barrier.cluster.wait.aligned;" ::: "memory");
}

__device__ __forceinline__ unsigned long long pack2(float lo, float hi) {
    unsigned long long p;
    asm("mov.b64 %0, {%1, %2};" : "=l"(p) : "f"(lo), "f"(hi));
    return p;
}

__device__ __forceinline__ void fma2(unsigned long long& acc,
                                     unsigned long long q,
                                     unsigned long long w) {
    asm("fma.rn.f32x2 %0, %1, %2, %0;" : "+l"(acc) : "l"(q), "l"(w));
}

__device__ __forceinline__ float sum2(unsigned long long p) {
    float lo, hi;
    asm("mov.b64 {%0, %1}, %2;" : "=f"(lo), "=f"(hi) : "l"(p));
    return lo + hi;
}

extern __shared__ float smem[];

__global__ void __launch_bounds__(NT, 1) __cluster_dims__(CLUSTER, 1, 1)
ctrnn_kernel(const float* __restrict__ x, const float* __restrict__ ic,
             const float* __restrict__ Win, const float* __restrict__ Wrec,
             const float* __restrict__ bias, const float* __restrict__ tau,
             const float* __restrict__ rw, const float* __restrict__ rb,
             float* __restrict__ out)
{
    const int tid = threadIdx.x;
    const int rank = (int)(blockIdx.x & (CLUSTER - 1));
    const int clid = (int)(blockIdx.x >> 3);
    const int hbase = rank * COLSn;
    const int rbase = clid * ROWSn;

    float* V  = smem + OFF_V;    // 2 x [ROWSn][KTOT]
    float* P  = smem + OFF_P;    // [r][kg][hh]
    float* Bs = smem + OFF_B;
    float* Di = smem + OFF_D;

    const int kg = tid >> 4;             // 0..15
    const int cg = tid & 15;             // 0..15 (4 cols)
    const int kbase = kg * KEXT;
    const int cbase = hbase + cg * 4;

    // ---- register weight tile, k-pair packed: w2[kk2][c] = {W[k][c], W[k+1][c]} ----
    unsigned long long w2[KP2][4];
    #pragma unroll
    for (int kk2 = 0; kk2 < KP2; ++kk2) {
        const int k = kbase + 2 * kk2;
        const float* s0 = (k < Hn) ? (Wrec + (size_t)k * Hn + cbase)
                                   : (Win + (size_t)(k - Hn) * Hn + cbase);
        const float* s1 = (k + 1 < Hn) ? (Wrec + (size_t)(k + 1) * Hn + cbase)
                                       : (Win + (size_t)(k + 1 - Hn) * Hn + cbase);
        float4 a = *reinterpret_cast<const float4*>(s0);
        float4 b = *reinterpret_cast<const float4*>(s1);
        w2[kk2][0] = pack2(a.x, b.x);
        w2[kk2][1] = pack2(a.y, b.y);
        w2[kk2][2] = pack2(a.z, b.z);
        w2[kk2][3] = pack2(a.w, b.w);
    }

    if (tid < COLSn) {
        Bs[tid] = bias[hbase + tid];
        Di[tid] = DTc / tau[hbase + tid];
    }
    // init state buffer 0 with trainable IC
    for (int i = tid; i < ROWSn * Hn; i += NT) {
        int r = i >> 9, k = i & (Hn - 1);
        V[r * KTOT + k] = ic[k];
    }
    // x[t=0] into buffer 0
    if (tid < 128) {
        int r = tid >> 5, j = tid & 31;
        const float4 xv = *reinterpret_cast<const float4*>(
            x + ((size_t)(rbase + r) * Tn) * Fn + 4 * j);
        *reinterpret_cast<float4*>(&V[r * KTOT + Hn + 4 * j]) = xv;
    }
    __syncthreads();

    const int fr = tid >> 6;
    const int fh = tid & 63;
    const float bi  = Bs[fh];
    const float dti = Di[fh];
    cluster_sync_all();

    int cur = 0;
    for (int t = 0; t < Tn; ++t) {
        float* vc = V + cur * (ROWSn * KTOT);
        float* vn = V + (cur ^ 1) * (ROWSn * KTOT);

        // ---- issue x[t+1] prefetch now; published by the step-ending cluster sync ----
        if (tid < 128 && t + 1 < Tn) {
            int r = tid >> 5, j = tid & 31;
            const float* src = x + ((size_t)(rbase + r) * Tn + (t + 1)) * Fn + 4 * j;
            unsigned dst = smem_u32(&vn[r * KTOT + Hn + 4 * j]);
            asm volatile("cp.async.cg.shared.global [%0], [%1], 16;"
                         :: "r"(dst), "l"(src));
            asm volatile("cp.async.commit_group;");
        }

        // ---- GEMV partial, all fma.rn.f32x2 ----
        const float* vkg = vc + kbase;
        unsigned long long acc[ROWSn][4];
        #pragma unroll
        for (int r = 0; r < ROWSn; ++r)
            { acc[r][0] = 0ULL; acc[r][1] = 0ULL; acc[r][2] = 0ULL; acc[r][3] = 0ULL; }

        #pragma unroll
        for (int kb = 0; kb < KEXT / 4; ++kb) {
            const unsigned long long wA0 = w2[2 * kb][0],     wA1 = w2[2 * kb][1];
            const unsigned long long wA2 = w2[2 * kb][2],     wA3 = w2[2 * kb][3];
            const unsigned long long wB0 = w2[2 * kb + 1][0], wB1 = w2[2 * kb + 1][1];
            const unsigned long long wB2 = w2[2 * kb + 1][2], wB3 = w2[2 * kb + 1][3];
            #pragma unroll
            for (int r = 0; r < ROWSn; ++r) {
                const ulonglong2 qq = *reinterpret_cast<const ulonglong2*>(
                    vkg + r * KTOT + kb * 4);     // (q0,q1), (q2,q3)
                fma2(acc[r][0], qq.x, wA0);
                fma2(acc[r][1], qq.x, wA1);
                fma2(acc[r][2], qq.x, wA2);
                fma2(acc[r][3], qq.x, wA3);
                fma2(acc[r][0], qq.y, wB0);
                fma2(acc[r][1], qq.y, wB1);
                fma2(acc[r][2], qq.y, wB2);
                fma2(acc[r][3], qq.y, wB3);
            }
        }
        // collapse packed halves + store partials (float4, conflict-free)
        #pragma unroll
        for (int r = 0; r < ROWSn; ++r) {
            *reinterpret_cast<float4*>(&P[(r * NKG + kg) * COLSn + cg * 4]) =
                make_float4(sum2(acc[r][0]), sum2(acc[r][1]),
                            sum2(acc[r][2]), sum2(acc[r][3]));
        }
        __syncthreads();

        // ---- reduce 16 partials, finalize, push s' to all 8 CTAs ----
        {
            const float* pr = &P[fr * NKG * COLSn + fh];
            float s0 = 0.f, s1 = 0.f;
            #pragma unroll
            for (int g = 0; g < NKG; g += 2) {
                s0 += pr[g * COLSn];
                s1 += pr[(g + 1) * COLSn];
            }
            float pre  = (s0 + s1) + bi;
            float sold = vc[fr * KTOT + hbase + fh];
            float th   = tanhf(pre);
            float sn   = sold + dti * (th - sold);
            unsigned my = smem_u32(&vn[fr * KTOT + hbase + fh]);
            #pragma unroll
            for (int c = 0; c < CLUSTER; ++c) {
                unsigned ra;
                asm("mapa.shared::cluster.u32 %0, %1, %2;" : "=r"(ra) : "r"(my), "r"(c));
                asm volatile("st.shared::cluster.f32 [%0], %1;" :: "r"(ra), "f"(sn));
            }
        }
        // complete my x-prefetch before publishing the step
        if (tid < 128) {
            asm volatile("cp.async.wait_group 0;");
        }
        cluster_sync_all();
        cur ^= 1;
    }

    // ---------------- readout (rank 0 of each cluster) ----------------
    if (rank == 0 && tid < ROWSn * On) {
        const int r = tid / On, o = tid - On * r;
        const float* s = V + cur * (ROWSn * KTOT) + r * KTOT;
        float c0 = 0.f, c1 = 0.f, c2 = 0.f, c3 = 0.f;
        #pragma unroll 8
        for (int k = 0; k < Hn; k += 4) {
            c0 = fmaf(s[k    ], rw[(k    ) * On + o], c0);
            c1 = fmaf(s[k + 1], rw[(k + 1) * On + o], c1);
            c2 = fmaf(s[k + 2], rw[(k + 2) * On + o], c2);
            c3 = fmaf(s[k + 3], rw[(k + 3) * On + o], c3);
        }
        out[(rbase + r) * On + o] = (c0 + c1) + (c2 + c3) + rb[o];
    }
}

extern "C" void kernel_launch(void* const* d_in, const int* in_sizes, int n_in,
                              void* d_out, int out_size) {
    const float* x    = (const float*)d_in[0];
    const float* ic   = (const float*)d_in[1];
    const float* Win  = (const float*)d_in[2];
    const float* Wrec = (const float*)d_in[3];
    const float* b    = (const float*)d_in[4];
    const float* tau  = (const float*)d_in[5];
    const float* rw   = (const float*)d_in[6];
    const float* rb   = (const float*)d_in[7];
    float* out = (float*)d_out;

    cudaFuncSetAttribute(ctrnn_kernel,
                         cudaFuncAttributeMaxDynamicSharedMemorySize, SMEM_BYTES);
    ctrnn_kernel<<<(Bn / ROWSn) * CLUSTER, NT, SMEM_BYTES>>>(
        x, ic, Win, Wrec, b, tau, rw, rb, out);
}

// round 7
// speedup vs baseline: 2.2166x; 1.2510x over previous
#include <cuda_runtime.h>

// Problem constants
#define Bn 64
#define Tn 4096
#define Fn 128
#define Hn 512
#define On 10
#define DTc 0.1f

// 16 clusters x 8 CTAs; cluster owns 4 batch rows; CTA owns a 64-column slice
// of H. Weights register-resident (f32x2-packed). Cross-CTA state exchange via
// st.async + transaction-counted mbarriers (full/empty ring) — no per-step
// barrier.cluster, no L1 flush, store latency overlapped with the wait.
#define CLUSTER 8
#define ROWSn 4
#define COLSn 64
#define KTOT 640           // Hn + Fn
#define NT 256
#define KEXT 40            // k-extent per thread
#define NKG 16             // k-groups
#define KP2 (KEXT / 2)     // packed k-pairs per thread

#define XCHG_BYTES (ROWSn * Hn * 4)   // 8192 B received per CTA per step

// SMEM layout (floats)
#define OFF_V 0                            // double-buffered [s(512);x(128)] per row
#define SZ_V (2 * ROWSn * KTOT)            // 5120
#define OFF_P (OFF_V + SZ_V)               // partials [r][kg][hh]
#define SZ_P (ROWSn * NKG * COLSn)         // 4096
#define OFF_B (OFF_P + SZ_P)
#define OFF_D (OFF_B + COLSn)
#define OFF_MB (OFF_D + COLSn)             // 4 mbarriers (full0,full1,empty0,empty1)
#define SMEM_FLOATS (OFF_MB + 8)
#define SMEM_BYTES (SMEM_FLOATS * 4)

__device__ __forceinline__ unsigned smem_u32(const void* p) {
    return (unsigned)__cvta_generic_to_shared(p);
}

__device__ __forceinline__ void cluster_sync_all() {
    asm volatile("barrier.cluster.arrive.aligned;\n\t"
                 "barrier.cluster.wait.aligned;" ::: "memory");
}

__device__ __forceinline__ unsigned long long pack2(float lo, float hi) {
    unsigned long long p;
    asm("mov.b64 %0, {%1, %2};" : "=l"(p) : "f"(lo), "f"(hi));
    return p;
}

__device__ __forceinline__ void fma2(unsigned long long& acc,
                                     unsigned long long q,
                                     unsigned long long w) {
    asm("fma.rn.f32x2 %0, %1, %2, %0;" : "+l"(acc) : "l"(q), "l"(w));
}

__device__ __forceinline__ float sum2(unsigned long long p) {
    float lo, hi;
    asm("mov.b64 {%0, %1}, %2;" : "=f"(lo), "=f"(hi) : "l"(p));
    return lo + hi;
}

// ---- mbarrier helpers ----
__device__ __forceinline__ void mbar_init(unsigned a, unsigned cnt) {
    asm volatile("mbarrier.init.shared.b64 [%0], %1;" :: "r"(a), "r"(cnt) : "memory");
}
__device__ __forceinline__ void mbar_arrive_local(unsigned a) {
    asm volatile("mbarrier.arrive.shared.b64 _, [%0];" :: "r"(a) : "memory");
}
__device__ __forceinline__ void mbar_arrive_remote(unsigned local_addr, unsigned rank) {
    asm volatile("{\n\t.reg .b32 ra;\n\t"
                 "mapa.shared::cluster.u32 ra, %0, %1;\n\t"
                 "mbarrier.arrive.shared::cluster.b64 _, [ra];\n\t}"
                 :: "r"(local_addr), "r"(rank) : "memory");
}
__device__ __forceinline__ void mbar_expect_tx(unsigned a, unsigned bytes) {
    asm volatile("mbarrier.arrive.expect_tx.shared.b64 _, [%0], %1;"
                 :: "r"(a), "r"(bytes) : "memory");
}
__device__ __forceinline__ void mbar_wait_parity(unsigned a, unsigned ph) {
    asm volatile(
        "{\n\t.reg .pred P1;\n\t"
        "WAIT_LOOP_%=:\n\t"
        "mbarrier.try_wait.parity.acquire.cta.shared::cta.b64 P1, [%0], %1, 0x989680;\n\t"
        "@P1 bra.uni WAIT_DONE_%=;\n\t"
        "bra.uni WAIT_LOOP_%=;\n\t"
        "WAIT_DONE_%=:\n\t}"
        :: "r"(a), "r"(ph) : "memory");
}
// store 4B into rank's smem, signaling rank's mbarrier with 4 tx bytes
__device__ __forceinline__ void st_async_remote(unsigned local_data_addr,
                                                unsigned local_mbar_addr,
                                                unsigned rank, float v) {
    asm volatile("{\n\t.reg .b32 ra, rb;\n\t"
                 "mapa.shared::cluster.u32 ra, %0, %2;\n\t"
                 "mapa.shared::cluster.u32 rb, %1, %2;\n\t"
                 "st.async.shared::cluster.mbarrier::complete_tx::bytes.f32 [ra], %3, [rb];\n\t}"
                 :: "r"(local_data_addr), "r"(local_mbar_addr), "r"(rank), "f"(v)
                 : "memory");
}

extern __shared__ float smem[];

__global__ void __launch_bounds__(NT, 1) __cluster_dims__(CLUSTER, 1, 1)
ctrnn_kernel(const float* __restrict__ x, const float* __restrict__ ic,
             const float* __restrict__ Win, const float* __restrict__ Wrec,
             const float* __restrict__ bias, const float* __restrict__ tau,
             const float* __restrict__ rw, const float* __restrict__ rb,
             float* __restrict__ out)
{
    const int tid = threadIdx.x;
    const int rank = (int)(blockIdx.x & (CLUSTER - 1));
    const int clid = (int)(blockIdx.x >> 3);
    const int hbase = rank * COLSn;
    const int rbase = clid * ROWSn;

    float* V  = smem + OFF_V;    // 2 x [ROWSn][KTOT]
    float* P  = smem + OFF_P;    // [r][kg][hh]
    float* Bs = smem + OFF_B;
    float* Di = smem + OFF_D;

    const unsigned mb_base = smem_u32(smem + OFF_MB);
    const unsigned mb_full0  = mb_base;
    const unsigned mb_full1  = mb_base + 8;
    const unsigned mb_empty0 = mb_base + 16;
    const unsigned mb_empty1 = mb_base + 24;

    const int kg = tid >> 4;             // 0..15
    const int cg = tid & 15;             // 0..15 (4 cols)
    const int kbase = kg * KEXT;
    const int cbase = hbase + cg * 4;

    // ---- register weight tile, k-pair packed ----
    unsigned long long w2[KP2][4];
    #pragma unroll
    for (int kk2 = 0; kk2 < KP2; ++kk2) {
        const int k = kbase + 2 * kk2;
        const float* s0 = (k < Hn) ? (Wrec + (size_t)k * Hn + cbase)
                                   : (Win + (size_t)(k - Hn) * Hn + cbase);
        const float* s1 = (k + 1 < Hn) ? (Wrec + (size_t)(k + 1) * Hn + cbase)
                                       : (Win + (size_t)(k + 1 - Hn) * Hn + cbase);
        float4 a = *reinterpret_cast<const float4*>(s0);
        float4 b = *reinterpret_cast<const float4*>(s1);
        w2[kk2][0] = pack2(a.x, b.x);
        w2[kk2][1] = pack2(a.y, b.y);
        w2[kk2][2] = pack2(a.z, b.z);
        w2[kk2][3] = pack2(a.w, b.w);
    }

    if (tid == 0) {
        mbar_init(mb_full0, 1);
        mbar_init(mb_full1, 1);
        mbar_init(mb_empty0, CLUSTER);
        mbar_init(mb_empty1, CLUSTER);
        asm volatile("fence.mbarrier_init.release.cluster;" ::: "memory");
    }
    if (tid < COLSn) {
        Bs[tid] = bias[hbase + tid];
        Di[tid] = DTc / tau[hbase + tid];
    }
    for (int i = tid; i < ROWSn * Hn; i += NT) {
        int r = i >> 9, k = i & (Hn - 1);
        V[r * KTOT + k] = ic[k];
    }
    if (tid < 128) {
        int r = tid >> 5, j = tid & 31;
        const float4 xv = *reinterpret_cast<const float4*>(
            x + ((size_t)(rbase + r) * Tn) * Fn + 4 * j);
        *reinterpret_cast<float4*>(&V[r * KTOT + Hn + 4 * j]) = xv;
    }
    __syncthreads();

    const int fr = tid >> 6;
    const int fh = tid & 63;
    const float bi  = Bs[fh];
    const float dti = Di[fh];

    cluster_sync_all();          // all inits visible cluster-wide
    if (tid == 0) {
        mbar_arrive_local(mb_full0);                  // pre-arm full[0] (phase 0)
        #pragma unroll
        for (int c = 0; c < CLUSTER; ++c)
            mbar_arrive_remote(mb_empty1, (unsigned)c); // pre-arm empty[1]
    }

    int phf0 = 0, phf1 = 0, phe0 = 0, phe1 = 0;

#define STEP_BODY(CUR, MBF_CUR, PHF_CUR, MBE_CUR, MBE_OTH, PHE_OTH, MBF_OTH, TT)       \
    {                                                                                   \
        float* vc = V + (CUR) * (ROWSn * KTOT);                                         \
        float* vn = V + ((CUR) ^ 1) * (ROWSn * KTOT);                                   \
        /* prefetch x[TT+1] into vn (published by this step's __syncthreads) */         \
        if (tid < 128 && (TT) + 1 < Tn) {                                               \
            int r = tid >> 5, j = tid & 31;                                             \
            const float* src = x + ((size_t)(rbase + r) * Tn + ((TT) + 1)) * Fn + 4 * j;\
            unsigned dst = smem_u32(&vn[r * KTOT + Hn + 4 * j]);                        \
            asm volatile("cp.async.cg.shared.global [%0], [%1], 16;"                    \
                         :: "r"(dst), "l"(src));                                        \
            asm volatile("cp.async.commit_group;");                                     \
        }                                                                               \
        /* wait for this step's input state (all 8192 exchange bytes landed) */         \
        mbar_wait_parity(MBF_CUR, (unsigned)(PHF_CUR)); (PHF_CUR) ^= 1;                 \
        /* GEMV partial, all fma.rn.f32x2 */                                            \
        const float* vkg = vc + kbase;                                                  \
        unsigned long long acc[ROWSn][4];                                               \
        _Pragma("unroll")                                                               \
        for (int r = 0; r < ROWSn; ++r)                                                 \
            { acc[r][0] = 0ULL; acc[r][1] = 0ULL; acc[r][2] = 0ULL; acc[r][3] = 0ULL; } \
        _Pragma("unroll")                                                               \
        for (int kb = 0; kb < KEXT / 4; ++kb) {                                         \
            const unsigned long long wA0 = w2[2 * kb][0],     wA1 = w2[2 * kb][1];      \
            const unsigned long long wA2 = w2[2 * kb][2],     wA3 = w2[2 * kb][3];      \
            const unsigned long long wB0 = w2[2 * kb + 1][0], wB1 = w2[2 * kb + 1][1];  \
            const unsigned long long wB2 = w2[2 * kb + 1][2], wB3 = w2[2 * kb + 1][3];  \
            _Pragma("unroll")                                                           \
            for (int r = 0; r < ROWSn; ++r) {                                           \
                const ulonglong2 qq = *reinterpret_cast<const ulonglong2*>(             \
                    vkg + r * KTOT + kb * 4);                                           \
                fma2(acc[r][0], qq.x, wA0);                                             \
                fma2(acc[r][1], qq.x, wA1);                                             \
                fma2(acc[r][2], qq.x, wA2);                                             \
                fma2(acc[r][3], qq.x, wA3);                                             \
                fma2(acc[r][0], qq.y, wB0);                                             \
                fma2(acc[r][1], qq.y, wB1);                                             \
                fma2(acc[r][2], qq.y, wB2);                                             \
                fma2(acc[r][3], qq.y, wB3);                                             \
            }                                                                           \
        }                                                                               \
        /* sold must be read before __syncthreads (peers may overwrite vc after */      \
        /* our empty[CUR] arrive below) */                                              \
        const float sold = vc[fr * KTOT + hbase + fh];                                  \
        _Pragma("unroll")                                                               \
        for (int r = 0; r < ROWSn; ++r) {                                               \
            *reinterpret_cast<float4*>(&P[(r * NKG + kg) * COLSn + cg * 4]) =           \
                make_float4(sum2(acc[r][0]), sum2(acc[r][1]),                           \
                            sum2(acc[r][2]), sum2(acc[r][3]));                          \
        }                                                                               \
        if (tid < 128) { asm volatile("cp.async.wait_group 0;"); }                      \
        __syncthreads();                                                                \
        /* all warps done reading vc -> tell everyone this buffer is consumable */      \
        if (tid == 0) {                                                                 \
            _Pragma("unroll")                                                           \
            for (int c = 0; c < CLUSTER; ++c)                                           \
                mbar_arrive_remote(MBE_CUR, (unsigned)c);                               \
        }                                                                               \
        /* reduce partials, finalize */                                                 \
        const float* pr = &P[fr * NKG * COLSn + fh];                                    \
        float s0 = 0.f, s1 = 0.f;                                                       \
        _Pragma("unroll")                                                               \
        for (int g = 0; g < NKG; g += 2) {                                              \
            s0 += pr[g * COLSn];                                                        \
            s1 += pr[(g + 1) * COLSn];                                                  \
        }                                                                               \
        float pre = (s0 + s1) + bi;                                                     \
        float th  = tanhf(pre);                                                         \
        float sn  = sold + dti * (th - sold);                                           \
        /* backpressure: peers must have consumed the buffer we now overwrite */        \
        mbar_wait_parity(MBE_OTH, (unsigned)(PHE_OTH)); (PHE_OTH) ^= 1;                 \
        if (tid == 0) mbar_expect_tx(MBF_OTH, XCHG_BYTES);                              \
        /* push s' to all 8 CTAs (incl. self), tx-counted on their full barrier */      \
        {                                                                               \
            unsigned my = smem_u32(&vn[fr * KTOT + hbase + fh]);                        \
            _Pragma("unroll")                                                           \
            for (int c = 0; c < CLUSTER; ++c)                                           \
                st_async_remote(my, MBF_OTH, (unsigned)c, sn);                          \
        }                                                                               \
    }

    for (int t = 0; t < Tn; t += 2) {
        STEP_BODY(0, mb_full0, phf0, mb_empty0, mb_empty1, phe1, mb_full1, t)
        STEP_BODY(1, mb_full1, phf1, mb_empty1, mb_empty0, phe0, mb_full0, t + 1)
    }
#undef STEP_BODY

    // final exchange (last step stored into buffer 0, signaling full[0])
    mbar_wait_parity(mb_full0, (unsigned)phf0);

    // ---------------- readout (rank 0 of each cluster) ----------------
    if (rank == 0 && tid < ROWSn * On) {
        const int r = tid / On, o = tid - On * r;
        const float* s = V + r * KTOT;           // buffer 0
        float c0 = 0.f, c1 = 0.f, c2 = 0.f, c3 = 0.f;
        #pragma unroll 8
        for (int k = 0; k < Hn; k += 4) {
            c0 = fmaf(s[k    ], rw[(k    ) * On + o], c0);
            c1 = fmaf(s[k + 1], rw[(k + 1) * On + o], c1);
            c2 = fmaf(s[k + 2], rw[(k + 2) * On + o], c2);
            c3 = fmaf(s[k + 3], rw[(k + 3) * On + o], c3);
        }
        out[(rbase + r) * On + o] = (c0 + c1) + (c2 + c3) + rb[o];
    }

    cluster_sync_all();   // no CTA exits while peers' DSMEM traffic may be in flight
}

extern "C" void kernel_launch(void* const* d_in, const int* in_sizes, int n_in,
                              void* d_out, int out_size) {
    const float* x    = (const float*)d_in[0];
    const float* ic   = (const float*)d_in[1];
    const float* Win  = (const float*)d_in[2];
    const float* Wrec = (const float*)d_in[3];
    const float* b    = (const float*)d_in[4];
    const float* tau  = (const float*)d_in[5];
    const float* rw   = (const float*)d_in[6];
    const float* rb   = (const float*)d_in[7];
    float* out = (float*)d_out;

    cudaFuncSetAttribute(ctrnn_kernel,
                         cudaFuncAttributeMaxDynamicSharedMemorySize, SMEM_BYTES);
    ctrnn_kernel<<<(Bn / ROWSn) * CLUSTER, NT, SMEM_BYTES>>>(
        x, ic, Win, Wrec, b, tau, rw, rb, out);
}